// round 15
// baseline (speedup 1.0000x reference)
#include <cuda_runtime.h>
#include <cuda_fp16.h>
#include <cstdint>
#include <cstddef>
#include <type_traits>

#define BATCH 8
#define CIN   128
#define HT    112
#define WD    112
#define COUT  256
#define HW    (HT*WD)

#define NT    112          // pixels per CTA (1 image row)
#define MT    256          // couts per CTA (all of them)
#define WROWS 338          // staged window rows (NT + 226)
#define RPB   64           // bytes per row (32 halves, conflict-free LDS.128)
#define WBUF  (WROWS*RPB)  // 21632
#define A_SZ  (MT*RPB)     // 16384
#define AOFF  (2*WBUF)     // 43264; 4 A buffers -> ends 108800
#define PC    116          // epilogue fp32 pitch
#define SINV_OFF  118784   // after c_s (256*116*4)
#define SCORR_OFF 119232   // 512 floats (L then R)
#define DSMEM     121280

__device__ float g_csum[BATCH*HW];
__device__ float g_corr[BATCH*HT*2*COUT];                    // [b][oy][side][co]
__device__ __align__(256) __half g_xt[(size_t)BATCH*HW*CIN]; // [b][p][ci_perm]
__device__ __align__(256) __half g_wh[36*COUT*32];           // [it][co][32ci_perm]

// permutation within a 32-ci chunk: both 16-groups' mma fragment pairs land in
// one 16B span per thread t: halfpos = t*8 + g16*4 + inner
__device__ __host__ __forceinline__ constexpr int permpos32(int c) {
    int k = c & 15, gg = c >> 4;
    return ((k & 7) >> 1) * 8 + gg * 4 + (((k >> 3) << 1) | (k & 1));
}

// ---------------------------------------------------------------------------
__device__ __forceinline__ uint32_t smem_u32(const void* p) {
    uint32_t a;
    asm("{ .reg .u64 t; cvta.to.shared.u64 t, %1; cvt.u32.u64 %0, t; }" : "=r"(a) : "l"(p));
    return a;
}
#define CP_COMMIT() asm volatile("cp.async.commit_group;" ::: "memory")
#define CP_WAIT(n)  asm volatile("cp.async.wait_group %0;" :: "n"(n) : "memory")

template <int IMM>
__device__ __forceinline__ void lds128i(uint32_t& x, uint32_t& y, uint32_t& z,
                                        uint32_t& w, uint32_t base) {
    asm volatile("ld.shared.v4.b32 {%0,%1,%2,%3}, [%4+%5];"
                 : "=r"(x), "=r"(y), "=r"(z), "=r"(w) : "r"(base), "n"(IMM));
}
__device__ __forceinline__ void mma16(float* c, uint32_t a0, uint32_t a1,
                                      uint32_t a2, uint32_t a3,
                                      uint32_t b0, uint32_t b1) {
    asm volatile(
        "mma.sync.aligned.m16n8k16.row.col.f32.f16.f16.f32 "
        "{%0,%1,%2,%3}, {%4,%5,%6,%7}, {%8,%9}, {%0,%1,%2,%3};"
        : "+f"(c[0]), "+f"(c[1]), "+f"(c[2]), "+f"(c[3])
        : "r"(a0), "r"(a1), "r"(a2), "r"(a3), "r"(b0), "r"(b1));
}

// compile-time for
template <int I, int N, typename F>
__device__ __forceinline__ void static_for(F&& f) {
    if constexpr (I < N) {
        f(std::integral_constant<int, I>{});
        static_for<I + 1, N>(f);
    }
}

// ---------------------------------------------------------------------------
// prep_x: channel sum-of-squares (fp32) + transpose to [b][p][ci_perm] half.
// ---------------------------------------------------------------------------
__global__ __launch_bounds__(128)
void prep_x(const float* __restrict__ x) {
    __shared__ __half sh[128][136];     // pad 8 halves: conflict-free STS/LDS.128
    const int tid = threadIdx.x;
    const int idx = blockIdx.x * 128 + tid;     // HW % 128 == 0 -> same b per blk
    const int b = idx / HW, p = idx - b * HW;
    const float* xp = x + (size_t)b * CIN * HW + p;

    float s = 0.f;
    __half hh[128];
#pragma unroll
    for (int c2 = 0; c2 < 4; ++c2)
#pragma unroll
        for (int k = 0; k < 32; ++k) {
            float v = xp[(c2 * 32 + k) * HW];
            s += v * v;
            hh[c2 * 32 + permpos32(k)] = __float2half_rn(v);
        }
    g_csum[idx] = s;
#pragma unroll
    for (int i = 0; i < 16; ++i)
        *(uint4*)&sh[tid][i * 8] = ((const uint4*)hh)[i];
    __syncthreads();

    uint4* dst = (uint4*)(g_xt + ((size_t)blockIdx.x * 128) * 128);
    for (int i = tid; i < 2048; i += 128) {
        int px = i >> 4, seg = i & 15;
        dst[i] = *(const uint4*)&sh[px][seg * 8];
    }
}

// g_wh[it][co][perm32] where it = cig*9 + pos
__global__ void wtrans_kernel(const float* __restrict__ w) {
    int idx = blockIdx.x * 256 + threadIdx.x;
    if (idx >= 9*CIN*COUT) return;
    int ci  = idx & 127;
    int r   = idx >> 7;
    int co  = r & 255;
    int pos = r >> 8;
    int it  = (ci >> 5) * 9 + pos;
    g_wh[((size_t)it*COUT + co)*32 + permpos32(ci & 31)] =
        __float2half_rn(w[((size_t)co*CIN + ci)*9 + pos]);
}

// ---------------------------------------------------------------------------
// corr_kernel: edge row-wrap correction (pre-inv), coalesced store to g_corr.
// ---------------------------------------------------------------------------
__global__ void corr_kernel() {
    const int side = blockIdx.z;
    const int b    = blockIdx.y;
    const int oc   = blockIdx.x * 16;
    const int co   = threadIdx.x;

    __shared__ __half xc[18][128];
    for (int i = threadIdx.x; i < 18 * 16; i += 256) {
        int r = i >> 4, seg = i & 15;
        int q = 0; bool v;
        if (side == 0) { int row = oc - 1 + r; v = (row >= 1 && row <= HT); q = row * WD - 1; }
        else           { int row = oc + r;     v = (row <= HT - 1);         q = row * WD;     }
        uint4 val = make_uint4(0, 0, 0, 0);
        if (v) val = *(const uint4*)(g_xt + ((size_t)b * HW + q) * 128 + seg * 8);
        *(uint4*)&xc[r][seg * 8] = val;
    }
    __syncthreads();

    const int kwsel = side ? 2 : 0;
    float corr[16];
#pragma unroll
    for (int dy = 0; dy < 16; ++dy) corr[dy] = 0.f;

#pragma unroll
    for (int kh = 0; kh < 3; ++kh) {
        const int pos = kh * 3 + kwsel;
        for (int cig = 0; cig < 4; ++cig) {
            const __half* wrow = g_wh + ((size_t)(cig * 9 + pos) * COUT + co) * 32;
#pragma unroll
            for (int c32 = 0; c32 < 32; ++c32) {
                float w = __half2float(wrow[c32]);
#pragma unroll
                for (int dy = 0; dy < 16; ++dy)
                    corr[dy] += w * __half2float(xc[dy + kh][cig * 32 + c32]);
            }
        }
    }

#pragma unroll
    for (int dy = 0; dy < 16; ++dy) {
        int oy = oc + dy;
        g_corr[(((size_t)b * HT + oy) * 2 + side) * COUT + co] = corr[dy];
    }
}

// ---------------------------------------------------------------------------
// Main conv GEMM: grid (112 rows, 8 batch), 256 threads, 1 CTA/SM.
// MT=256 per CTA; 8 warps as 4 m-groups (M64/warp) x 2 n-groups (N56).
// Per warp-tap: 8 A-LDS + 7 B-LDS -> 56 MMAs (half the LDS bytes per MMA of
// the previous M32 layout). static_for-unrolled; sync every 2 taps; 4-deep
// A pipeline; double-buffered window; fused inv-norm + edge-corr epilogue.
// ---------------------------------------------------------------------------
__global__ __launch_bounds__(256, 1)
void conv_mma_kernel(const float* __restrict__ bias, float* __restrict__ out) {
    extern __shared__ __align__(16) char dyn[];
    const uint32_t sbase = smem_u32(dyn);
    float* sInvF = (float*)(dyn + SINV_OFF);
    float* sCorr = (float*)(dyn + SCORR_OFF);   // [0..255]=left, [256..511]=right

    const int tid  = threadIdx.x;
    const int wid  = tid >> 5;
    const int lane = tid & 31;
    const int t    = lane & 3;
    const int g    = lane >> 2;
    const int m0w  = (wid & 3) * 64;
    const int n0w  = (wid >> 2) * 56;

    const int oy  = blockIdx.x;
    const int p0  = oy * NT;
    const int b   = blockIdx.y;
    const __half* xtb = g_xt + (size_t)b * HW * 128;

    // inv-norm for this row, straight from csum (box-sum + rsqrt)
    if (tid < NT) {
        float s = 0.f;
#pragma unroll
        for (int dy = -1; dy <= 1; ++dy) {
            int y = oy + dy; if ((unsigned)y >= HT) continue;
#pragma unroll
            for (int dx = -1; dx <= 1; ++dx) {
                int xq = tid + dx; if ((unsigned)xq >= WD) continue;
                s += g_csum[b * HW + y * WD + xq];
            }
        }
        sInvF[tid] = 1.f / fmaxf(sqrtf(s), 1e-12f);
    }
    // edge corrections for this row (both sides, all 256 couts)
#pragma unroll
    for (int i = tid; i < 512; i += 256) {
        int side = i >> 8, co = i & 255;
        sCorr[i] = g_corr[(((size_t)b * HT + oy) * 2 + side) * COUT + co];
    }

    float acc[4][7][4];
#pragma unroll
    for (int mi = 0; mi < 4; ++mi)
#pragma unroll
        for (int ni = 0; ni < 7; ++ni)
#pragma unroll
            for (int q = 0; q < 4; ++q) acc[mi][ni][q] = 0.f;

    // thread-constant base addresses (all per-tap offsets are LDS immediates)
    const uint32_t aTh = sbase + AOFF + (uint32_t)((m0w + g) * RPB + t * 16);
    const uint32_t bTh = sbase + (uint32_t)((n0w + g) * RPB + t * 16);
    const uint32_t aDst = sbase + AOFF + (uint32_t)tid * 64;

    auto issueW = [&](int cig) {
        uint32_t wB = sbase + (uint32_t)(cig & 1) * WBUF;
        for (int i = tid; i < WROWS * 4; i += 256) {
            int j = i >> 2, seg = i & 3;
            int q = p0 - 113 + j;
            unsigned ok = ((unsigned)q < (unsigned)HW) ? 16u : 0u;
            int qc = q < 0 ? 0 : (q >= HW ? HW - 1 : q);
            const __half* src = xtb + (size_t)qc * 128 + cig * 32 + seg * 8;
            asm volatile("cp.async.cg.shared.global [%0], [%1], 16, %2;"
                         :: "r"(wB + (uint32_t)(j * RPB + seg * 16)), "l"(src), "r"(ok));
        }
    };
    auto issueA = [&](auto itc) {
        constexpr int it2 = decltype(itc)::value;
        constexpr int dimm = (it2 & 3) * A_SZ;
        const __half* src = g_wh + ((size_t)it2 * COUT + tid) * 32;
        asm volatile("cp.async.cg.shared.global [%0+%4], [%1], 16;\n\t"
                     "cp.async.cg.shared.global [%0+%5], [%2], 16;\n\t"
                     "cp.async.cg.shared.global [%0+%6], [%3], 16;"
                     :: "r"(aDst), "l"(src), "l"(src + 8), "l"(src + 16),
                        "n"(dimm), "n"(dimm + 16), "n"(dimm + 32));
        asm volatile("cp.async.cg.shared.global [%0+%2], [%1], 16;"
                     :: "r"(aDst), "l"(src + 24), "n"(dimm + 48));
    };

    issueW(0); issueA(std::integral_constant<int, 0>{}); CP_COMMIT();
    issueA(std::integral_constant<int, 1>{}); CP_COMMIT();

    static_for<0, 36>([&](auto itc) {
        constexpr int it  = decltype(itc)::value;
        constexpr int tap = it % 9, cig = it / 9;

        if constexpr (it + 2 < 36) issueA(std::integral_constant<int, it + 2>{});
        if constexpr (tap == 4 && cig < 3) issueW(cig + 1);
        CP_COMMIT();
        if constexpr ((it & 1) == 0) {
            CP_WAIT(1);
            __syncthreads();
        }

        constexpr int dlt  = (tap / 3) * WD + (tap % 3);
        constexpr int aimm = (it & 3) * A_SZ;
        constexpr int bimm = (cig & 1) * WBUF + dlt * RPB;

        uint32_t a0[4][2], a1[4][2], a2[4][2], a3[4][2];  // [mi][ks]
        static_for<0, 4>([&](auto mic) {
            constexpr int mi = decltype(mic)::value;
            lds128i<aimm + mi * 1024>(a0[mi][0], a2[mi][0], a0[mi][1], a2[mi][1], aTh);
            lds128i<aimm + mi * 1024 + 512>(a1[mi][0], a3[mi][0], a1[mi][1], a3[mi][1], aTh);
        });

        static_for<0, 7>([&](auto nic) {
            constexpr int ni = decltype(nic)::value;
            uint32_t b0k0, b1k0, b0k1, b1k1;
            lds128i<bimm + ni * 512>(b0k0, b1k0, b0k1, b1k1, bTh);
            static_for<0, 4>([&](auto mic) {
                constexpr int mi = decltype(mic)::value;
                mma16(acc[mi][ni], a0[mi][0], a1[mi][0], a2[mi][0], a3[mi][0], b0k0, b1k0);
                mma16(acc[mi][ni], a0[mi][1], a1[mi][1], a2[mi][1], a3[mi][1], b0k1, b1k1);
            });
        });
    });
    __syncthreads();

    // --- epilogue: accum -> smem -> scaled, biased, edge-fixed, coalesced STG
    float* c_s = (float*)dyn;
#pragma unroll
    for (int mi = 0; mi < 4; ++mi)
#pragma unroll
        for (int ni = 0; ni < 7; ++ni) {
            const int m = m0w + mi * 16 + g;
            const int n = n0w + ni * 8 + 2 * t;
            c_s[m * PC + n]           = acc[mi][ni][0];
            c_s[m * PC + n + 1]       = acc[mi][ni][1];
            c_s[(m + 8) * PC + n]     = acc[mi][ni][2];
            c_s[(m + 8) * PC + n + 1] = acc[mi][ni][3];
        }
    __syncthreads();

    {
        const int m  = tid;                   // one cout per thread
        const float bv = bias[m];
        const float invL = sInvF[0], invR = sInvF[111];
        const float cL = sCorr[m] * invL, cR = sCorr[256 + m] * invR;
        float* op = out + ((size_t)b * COUT + m) * HW + p0;
#pragma unroll
        for (int j4 = 0; j4 < 28; ++j4) {
            float4 v = *(const float4*)&c_s[m * PC + j4 * 4];
            float4 r;
            r.x = v.x * sInvF[j4 * 4 + 0] + bv;
            r.y = v.y * sInvF[j4 * 4 + 1] + bv;
            r.z = v.z * sInvF[j4 * 4 + 2] + bv;
            r.w = v.w * sInvF[j4 * 4 + 3] + bv;
            if (j4 == 0)  r.x -= cL;          // ox = 0
            if (j4 == 27) r.w -= cR;          // ox = 111
            *(float4*)&op[j4 * 4] = r;
        }
    }
}

// ---------------------------------------------------------------------------
extern "C" void kernel_launch(void* const* d_in, const int* in_sizes, int n_in,
                              void* d_out, int out_size) {
    const float* x    = (const float*)d_in[0];
    const float* wgt  = (const float*)d_in[1];
    const float* bias = (const float*)d_in[2];
    float* out        = (float*)d_out;

    cudaFuncSetAttribute(conv_mma_kernel,
                         cudaFuncAttributeMaxDynamicSharedMemorySize, DSMEM);

    int npix = BATCH * HW;
    prep_x<<<npix / 128, 128>>>(x);
    wtrans_kernel<<<(9 * CIN * COUT + 255) / 256, 256>>>(wgt);
    corr_kernel<<<dim3(7, 8, 2), 256>>>();

    conv_mma_kernel<<<dim3(112, 8), 256, DSMEM>>>(bias, out);
}

// round 17
// speedup vs baseline: 1.4631x; 1.4631x over previous
#include <cuda_runtime.h>
#include <cuda_fp16.h>
#include <cstdint>
#include <cstddef>
#include <type_traits>

#define BATCH 8
#define CIN   128
#define HT    112
#define WD    112
#define COUT  256
#define HW    (HT*WD)

#define NT    112          // pixels per CTA (1 image row)
#define MT    128          // couts per CTA
#define WROWS 338          // staged window rows (NT + 226)
#define RPB   64           // bytes per row (32 halves, conflict-free LDS.128)
#define WBUF  (WROWS*RPB)  // 21632
#define A_SZ  (MT*RPB)     // 8192
#define AOFF  (2*WBUF)     // 43264; 8 A buffers -> ends 108800
#define PC    116          // epilogue fp32 pitch
#define SINV_OFF  108800   // 112 floats
#define SCORR_OFF 109312   // 256 floats (L then R)
#define DSMEM     110336

__device__ float g_csum[BATCH*HW];
__device__ float g_corr[BATCH*HT*2*COUT];                    // [b][oy][side][co]
__device__ __align__(256) __half g_xt[(size_t)BATCH*HW*CIN]; // [b][p][ci_perm]
__device__ __align__(256) __half g_wh[36*COUT*32];           // [it][co][32ci_perm]

// permutation within a 32-ci chunk: both 16-groups' mma fragment pairs land in
// one 16B span per thread t: halfpos = t*8 + g16*4 + inner
__device__ __host__ __forceinline__ constexpr int permpos32(int c) {
    int k = c & 15, gg = c >> 4;
    return ((k & 7) >> 1) * 8 + gg * 4 + (((k >> 3) << 1) | (k & 1));
}

// ---------------------------------------------------------------------------
__device__ __forceinline__ uint32_t smem_u32(const void* p) {
    uint32_t a;
    asm("{ .reg .u64 t; cvta.to.shared.u64 t, %1; cvt.u32.u64 %0, t; }" : "=r"(a) : "l"(p));
    return a;
}
#define CP_COMMIT() asm volatile("cp.async.commit_group;" ::: "memory")
#define CP_WAIT(n)  asm volatile("cp.async.wait_group %0;" :: "n"(n) : "memory")

template <int IMM>
__device__ __forceinline__ void lds128i(uint32_t& x, uint32_t& y, uint32_t& z,
                                        uint32_t& w, uint32_t base) {
    asm volatile("ld.shared.v4.b32 {%0,%1,%2,%3}, [%4+%5];"
                 : "=r"(x), "=r"(y), "=r"(z), "=r"(w) : "r"(base), "n"(IMM));
}
__device__ __forceinline__ void mma16(float* c, uint32_t a0, uint32_t a1,
                                      uint32_t a2, uint32_t a3,
                                      uint32_t b0, uint32_t b1) {
    asm volatile(
        "mma.sync.aligned.m16n8k16.row.col.f32.f16.f16.f32 "
        "{%0,%1,%2,%3}, {%4,%5,%6,%7}, {%8,%9}, {%0,%1,%2,%3};"
        : "+f"(c[0]), "+f"(c[1]), "+f"(c[2]), "+f"(c[3])
        : "r"(a0), "r"(a1), "r"(a2), "r"(a3), "r"(b0), "r"(b1));
}

// compile-time for
template <int I, int N, typename F>
__device__ __forceinline__ void static_for(F&& f) {
    if constexpr (I < N) {
        f(std::integral_constant<int, I>{});
        static_for<I + 1, N>(f);
    }
}

// ---------------------------------------------------------------------------
// prep_x: channel sum-of-squares (fp32) + transpose to [b][p][ci_perm] half.
// ---------------------------------------------------------------------------
__global__ __launch_bounds__(128)
void prep_x(const float* __restrict__ x) {
    __shared__ __half sh[128][136];     // pad 8 halves: conflict-free STS/LDS.128
    const int tid = threadIdx.x;
    const int idx = blockIdx.x * 128 + tid;     // HW % 128 == 0 -> same b per blk
    const int b = idx / HW, p = idx - b * HW;
    const float* xp = x + (size_t)b * CIN * HW + p;

    float s = 0.f;
    __half hh[128];
#pragma unroll
    for (int c2 = 0; c2 < 4; ++c2)
#pragma unroll
        for (int k = 0; k < 32; ++k) {
            float v = xp[(c2 * 32 + k) * HW];
            s += v * v;
            hh[c2 * 32 + permpos32(k)] = __float2half_rn(v);
        }
    g_csum[idx] = s;
#pragma unroll
    for (int i = 0; i < 16; ++i)
        *(uint4*)&sh[tid][i * 8] = ((const uint4*)hh)[i];
    __syncthreads();

    uint4* dst = (uint4*)(g_xt + ((size_t)blockIdx.x * 128) * 128);
    for (int i = tid; i < 2048; i += 128) {
        int px = i >> 4, seg = i & 15;
        dst[i] = *(const uint4*)&sh[px][seg * 8];
    }
}

// g_wh[it][co][perm32] where it = cig*9 + pos
__global__ void wtrans_kernel(const float* __restrict__ w) {
    int idx = blockIdx.x * 256 + threadIdx.x;
    if (idx >= 9*CIN*COUT) return;
    int ci  = idx & 127;
    int r   = idx >> 7;
    int co  = r & 255;
    int pos = r >> 8;
    int it  = (ci >> 5) * 9 + pos;
    g_wh[((size_t)it*COUT + co)*32 + permpos32(ci & 31)] =
        __float2half_rn(w[((size_t)co*CIN + ci)*9 + pos]);
}

// ---------------------------------------------------------------------------
// corr_kernel: edge row-wrap correction (pre-inv), coalesced store to g_corr.
// ---------------------------------------------------------------------------
__global__ void corr_kernel() {
    const int side = blockIdx.z;
    const int b    = blockIdx.y;
    const int oc   = blockIdx.x * 16;
    const int co   = threadIdx.x;

    __shared__ __half xc[18][128];
    for (int i = threadIdx.x; i < 18 * 16; i += 256) {
        int r = i >> 4, seg = i & 15;
        int q = 0; bool v;
        if (side == 0) { int row = oc - 1 + r; v = (row >= 1 && row <= HT); q = row * WD - 1; }
        else           { int row = oc + r;     v = (row <= HT - 1);         q = row * WD;     }
        uint4 val = make_uint4(0, 0, 0, 0);
        if (v) val = *(const uint4*)(g_xt + ((size_t)b * HW + q) * 128 + seg * 8);
        *(uint4*)&xc[r][seg * 8] = val;
    }
    __syncthreads();

    const int kwsel = side ? 2 : 0;
    float corr[16];
#pragma unroll
    for (int dy = 0; dy < 16; ++dy) corr[dy] = 0.f;

#pragma unroll
    for (int kh = 0; kh < 3; ++kh) {
        const int pos = kh * 3 + kwsel;
        for (int cig = 0; cig < 4; ++cig) {
            const __half* wrow = g_wh + ((size_t)(cig * 9 + pos) * COUT + co) * 32;
#pragma unroll
            for (int c32 = 0; c32 < 32; ++c32) {
                float w = __half2float(wrow[c32]);
#pragma unroll
                for (int dy = 0; dy < 16; ++dy)
                    corr[dy] += w * __half2float(xc[dy + kh][cig * 32 + c32]);
            }
        }
    }

#pragma unroll
    for (int dy = 0; dy < 16; ++dy) {
        int oy = oc + dy;
        g_corr[(((size_t)b * HT + oy) * 2 + side) * COUT + co] = corr[dy];
    }
}

// ---------------------------------------------------------------------------
// Main conv GEMM: grid (112 rows, 2 cout-tiles, 8 batch), 256 threads,
// 2 CTAs/SM, warp tile M32xN56 (proven best). static_for-unrolled; ONE
// barrier per 4 taps with an 8-deep cp.async A ring (issue A(it+4) at tap
// it); double-buffered window; fused inv-norm + edge-correction epilogue.
// ---------------------------------------------------------------------------
__global__ __launch_bounds__(256, 2)
void conv_mma_kernel(const float* __restrict__ bias, float* __restrict__ out) {
    extern __shared__ __align__(16) char dyn[];
    const uint32_t sbase = smem_u32(dyn);
    float* sInvF = (float*)(dyn + SINV_OFF);
    float* sCorr = (float*)(dyn + SCORR_OFF);   // [0..127]=left, [128..255]=right

    const int tid  = threadIdx.x;
    const int wid  = tid >> 5;
    const int lane = tid & 31;
    const int t    = lane & 3;
    const int g    = lane >> 2;
    const int m0w  = (wid & 3) * 32;
    const int n0w  = (wid >> 2) * 56;

    const int oy  = blockIdx.x;
    const int p0  = oy * NT;
    const int co0 = blockIdx.y * MT;
    const int b   = blockIdx.z;
    const __half* xtb = g_xt + (size_t)b * HW * 128;

    // inv-norm for this row, straight from csum (box-sum + rsqrt)
    if (tid < NT) {
        float s = 0.f;
#pragma unroll
        for (int dy = -1; dy <= 1; ++dy) {
            int y = oy + dy; if ((unsigned)y >= HT) continue;
#pragma unroll
            for (int dx = -1; dx <= 1; ++dx) {
                int xq = tid + dx; if ((unsigned)xq >= WD) continue;
                s += g_csum[b * HW + y * WD + xq];
            }
        }
        sInvF[tid] = 1.f / fmaxf(sqrtf(s), 1e-12f);
    }
    // edge corrections for this row / cout-tile
    {
        int side = tid >> 7;          // 0: left, 1: right
        int co   = tid & 127;
        sCorr[tid] = g_corr[(((size_t)b * HT + oy) * 2 + side) * COUT + co0 + co];
    }

    float acc[2][7][4];
#pragma unroll
    for (int mi = 0; mi < 2; ++mi)
#pragma unroll
        for (int ni = 0; ni < 7; ++ni)
#pragma unroll
            for (int q = 0; q < 4; ++q) acc[mi][ni][q] = 0.f;

    // thread-constant base addresses (all per-tap offsets are LDS immediates)
    const uint32_t aTh = sbase + AOFF + (uint32_t)((m0w + g) * RPB + t * 16);
    const uint32_t bTh = sbase + (uint32_t)((n0w + g) * RPB + t * 16);
    const uint32_t aDst = sbase + AOFF + (uint32_t)tid * 32;

    auto issueW = [&](int cig) {
        uint32_t wB = sbase + (uint32_t)(cig & 1) * WBUF;
        for (int i = tid; i < WROWS * 4; i += 256) {
            int j = i >> 2, seg = i & 3;
            int q = p0 - 113 + j;
            unsigned ok = ((unsigned)q < (unsigned)HW) ? 16u : 0u;
            int qc = q < 0 ? 0 : (q >= HW ? HW - 1 : q);
            const __half* src = xtb + (size_t)qc * 128 + cig * 32 + seg * 8;
            asm volatile("cp.async.cg.shared.global [%0], [%1], 16, %2;"
                         :: "r"(wB + (uint32_t)(j * RPB + seg * 16)), "l"(src), "r"(ok));
        }
    };
    auto issueA = [&](auto itc) {
        constexpr int it2 = decltype(itc)::value;
        constexpr int dimm = (it2 & 7) * A_SZ;
        const __half* src = g_wh + ((size_t)it2 * COUT + co0) * 32 + (size_t)tid * 16;
        asm volatile("cp.async.cg.shared.global [%0+%3], [%1], 16;\n\t"
                     "cp.async.cg.shared.global [%0+%4], [%2], 16;"
                     :: "r"(aDst), "l"(src), "l"(src + 8),
                        "n"(dimm), "n"(dimm + 16));
    };

    // prologue: window 0 + A(0..3)
    issueW(0);
    issueA(std::integral_constant<int, 0>{});
    issueA(std::integral_constant<int, 1>{});
    issueA(std::integral_constant<int, 2>{});
    issueA(std::integral_constant<int, 3>{});
    CP_COMMIT();

    static_for<0, 36>([&](auto itc) {
        constexpr int it  = decltype(itc)::value;
        constexpr int tap = it % 9, cig = it / 9;

        if constexpr ((it & 3) == 0) {
            CP_WAIT(0);                 // drains A(it..it+3) (+window); issued >=1 tap ago
            __syncthreads();
        }
        if constexpr (it + 4 < 36) issueA(std::integral_constant<int, it + 4>{});
        if constexpr (tap == 4 && cig < 3) issueW(cig + 1);
        CP_COMMIT();

        constexpr int dlt  = (tap / 3) * WD + (tap % 3);
        constexpr int aimm = (it & 7) * A_SZ;
        constexpr int bimm = (cig & 1) * WBUF + dlt * RPB;

        uint32_t a0[2][2], a1[2][2], a2[2][2], a3[2][2];  // [mi][ks]
        lds128i<aimm>(a0[0][0], a2[0][0], a0[0][1], a2[0][1], aTh);
        lds128i<aimm + 512>(a1[0][0], a3[0][0], a1[0][1], a3[0][1], aTh);
        lds128i<aimm + 1024>(a0[1][0], a2[1][0], a0[1][1], a2[1][1], aTh);
        lds128i<aimm + 1536>(a1[1][0], a3[1][0], a1[1][1], a3[1][1], aTh);

        static_for<0, 7>([&](auto nic) {
            constexpr int ni = decltype(nic)::value;
            uint32_t b0k0, b1k0, b0k1, b1k1;
            lds128i<bimm + ni * 512>(b0k0, b1k0, b0k1, b1k1, bTh);
            mma16(acc[0][ni], a0[0][0], a1[0][0], a2[0][0], a3[0][0], b0k0, b1k0);
            mma16(acc[1][ni], a0[1][0], a1[1][0], a2[1][0], a3[1][0], b0k0, b1k0);
            mma16(acc[0][ni], a0[0][1], a1[0][1], a2[0][1], a3[0][1], b0k1, b1k1);
            mma16(acc[1][ni], a0[1][1], a1[1][1], a2[1][1], a3[1][1], b0k1, b1k1);
        });
    });
    __syncthreads();

    // --- epilogue: accum -> smem -> scaled, biased, edge-fixed, coalesced STG
    float* c_s = (float*)dyn;
#pragma unroll
    for (int mi = 0; mi < 2; ++mi)
#pragma unroll
        for (int ni = 0; ni < 7; ++ni) {
            const int m = m0w + mi * 16 + g;
            const int n = n0w + ni * 8 + 2 * t;
            c_s[m * PC + n]           = acc[mi][ni][0];
            c_s[m * PC + n + 1]       = acc[mi][ni][1];
            c_s[(m + 8) * PC + n]     = acc[mi][ni][2];
            c_s[(m + 8) * PC + n + 1] = acc[mi][ni][3];
        }
    __syncthreads();

    {
        const int m  = tid >> 1;
        const int cb = (tid & 1) * 56;
        const float bv = bias[co0 + m];
        float* op = out + ((size_t)b * COUT + co0 + m) * HW + p0 + cb;
#pragma unroll
        for (int j4 = 0; j4 < 14; ++j4) {
            float4 v = *(const float4*)&c_s[m * PC + cb + j4 * 4];
            float4 r;
            r.x = v.x * sInvF[cb + j4 * 4 + 0] + bv;
            r.y = v.y * sInvF[cb + j4 * 4 + 1] + bv;
            r.z = v.z * sInvF[cb + j4 * 4 + 2] + bv;
            r.w = v.w * sInvF[cb + j4 * 4 + 3] + bv;
            if (cb == 0 && j4 == 0)    r.x -= sCorr[m] * sInvF[0];          // ox=0
            if (cb == 56 && j4 == 13)  r.w -= sCorr[128 + m] * sInvF[111];  // ox=111
            *(float4*)&op[j4 * 4] = r;
        }
    }
}

// ---------------------------------------------------------------------------
extern "C" void kernel_launch(void* const* d_in, const int* in_sizes, int n_in,
                              void* d_out, int out_size) {
    const float* x    = (const float*)d_in[0];
    const float* wgt  = (const float*)d_in[1];
    const float* bias = (const float*)d_in[2];
    float* out        = (float*)d_out;

    cudaFuncSetAttribute(conv_mma_kernel,
                         cudaFuncAttributeMaxDynamicSharedMemorySize, DSMEM);

    int npix = BATCH * HW;
    prep_x<<<npix / 128, 128>>>(x);
    wtrans_kernel<<<(9 * CIN * COUT + 255) / 256, 256>>>(wgt);
    corr_kernel<<<dim3(7, 8, 2), 256>>>();

    conv_mma_kernel<<<dim3(112, 2, 8), 256, DSMEM>>>(bias, out);
}